// round 4
// baseline (speedup 1.0000x reference)
#include <cuda_runtime.h>
#include <math.h>

// Problem constants
#define BATCH 8
#define NSEQ  2048
#define HDIM  128
#define NROWS (BATCH * NSEQ)   // 16384

// Scratch (device globals: no allocation allowed)
__device__ float g_A[NROWS * HDIM];    // h after linear (input to aggregation)
__device__ float g_B[NROWS * HDIM];    // h after aggregation (input to next linear)
__device__ float g_inv[NROWS];         // 1 / max(||h_row||, eps)

// ---------------------------------------------------------------------------
// Kernel 1: H = X @ W + b, plus per-row inverse L2 norm.
// Tile: 64 rows x 128 cols, K=128. 256 threads, 8x4 register micro-tile.
// ---------------------------------------------------------------------------
__global__ __launch_bounds__(256, 2)
void gemm_norm_kernel(const float* __restrict__ X, const float* __restrict__ W,
                      const float* __restrict__ bias, float* __restrict__ H,
                      float* __restrict__ invn)
{
    __shared__ float xs[64 * 132];
    const int tid = threadIdx.x;
    const int row0 = blockIdx.x * 64;

    // Load X tile [64 x 128] into shared (stride 132 to dodge bank conflicts)
#pragma unroll
    for (int m = 0; m < 8; m++) {
        int idx = tid + 256 * m;
        int r = idx >> 5, c4 = (idx & 31) << 2;
        float4 v = *(const float4*)(X + (size_t)(row0 + r) * HDIM + c4);
        *(float4*)(xs + r * 132 + c4) = v;
    }
    __syncthreads();

    const int cx = tid & 31;   // 4 output cols at 4*cx  (warp = fixed ry)
    const int ry = tid >> 5;   // 8 rows at 8*ry+i

    float4 b4 = *(const float4*)(bias + cx * 4);
    float acc[8][4];
#pragma unroll
    for (int i = 0; i < 8; i++) {
        acc[i][0] = b4.x; acc[i][1] = b4.y; acc[i][2] = b4.z; acc[i][3] = b4.w;
    }

#pragma unroll 4
    for (int k = 0; k < 128; k++) {
        float4 w4 = *(const float4*)(W + k * HDIM + cx * 4);   // L1-resident
#pragma unroll
        for (int i = 0; i < 8; i++) {
            float xv = xs[(8 * ry + i) * 132 + k];             // broadcast LDS
            acc[i][0] = fmaf(xv, w4.x, acc[i][0]);
            acc[i][1] = fmaf(xv, w4.y, acc[i][1]);
            acc[i][2] = fmaf(xv, w4.z, acc[i][2]);
            acc[i][3] = fmaf(xv, w4.w, acc[i][3]);
        }
    }

    // Store + per-row sumsq reduction (row 8*ry+i lives entirely in warp ry)
#pragma unroll
    for (int i = 0; i < 8; i++) {
        int r = row0 + 8 * ry + i;
        float ss = acc[i][0] * acc[i][0] + acc[i][1] * acc[i][1]
                 + acc[i][2] * acc[i][2] + acc[i][3] * acc[i][3];
#pragma unroll
        for (int o = 16; o > 0; o >>= 1) ss += __shfl_xor_sync(0xffffffffu, ss, o);
        if (cx == 0) invn[r] = 1.0f / fmaxf(sqrtf(ss), 1e-12f);
        float4 o4 = make_float4(acc[i][0], acc[i][1], acc[i][2], acc[i][3]);
        *(float4*)(H + (size_t)r * HDIM + cx * 4) = o4;
    }
}

// ---------------------------------------------------------------------------
// Kernel 2: fused  out[p,:] = sum_q ew[p,q] * (nh_p . nh_q) * h[q,:]
// One CTA: 64 p-rows x 128 cols output; loop over 32 q-tiles of 64.
//   stage 1: S[p][q] = (hp_scaled . hq) * inv_q * ew[p][q]
//   stage 2: oacc    += S @ hq
// ---------------------------------------------------------------------------
#define SMEM_FLOATS (8448 + 8448 + 4352 + 64)   // hp, hq, S, invq = 85248 B

template<bool RELU>
__global__ __launch_bounds__(256, 2)
void agg_kernel(const float* __restrict__ H, const float* __restrict__ EW,
                const float* __restrict__ invn, float* __restrict__ OUT)
{
    extern __shared__ float sm[];
    float* sh_hp = sm;               // [64][132], pre-scaled by inv_p
    float* sh_hq = sm + 8448;        // [64][132], raw
    float* sh_S  = sm + 16896;       // [64][68]
    float* sh_iq = sm + 21248;       // [64]

    const int tid = threadIdx.x;
    const int b   = blockIdx.y;
    const int p0  = blockIdx.x * 64;
    const float* Hb  = H + (size_t)b * NSEQ * HDIM;
    const float* ivb = invn + b * NSEQ;
    const float* EWb = EW + (size_t)b * NSEQ * NSEQ;

    // Load hp tile, folding inv_p
#pragma unroll
    for (int m = 0; m < 8; m++) {
        int idx = tid + 256 * m;
        int r = idx >> 5, c4 = (idx & 31) << 2;
        float iv = ivb[p0 + r];
        float4 v = *(const float4*)(Hb + (size_t)(p0 + r) * HDIM + c4);
        v.x *= iv; v.y *= iv; v.z *= iv; v.w *= iv;
        *(float4*)(sh_hp + r * 132 + c4) = v;
    }

    const int tq = tid & 15, tp = tid >> 4;   // stage-1 layout (16x16, 4x4 micro)
    const int cx = tid & 31, py = tid >> 5;   // stage-2 layout (warp = fixed py)

    float oacc[8][4];
#pragma unroll
    for (int i = 0; i < 8; i++)
#pragma unroll
        for (int j = 0; j < 4; j++) oacc[i][j] = 0.0f;

    __syncthreads();

    for (int qt = 0; qt < 32; qt++) {
        const int q0 = qt * 64;

        // Load hq tile (raw) + inv_q
#pragma unroll
        for (int m = 0; m < 8; m++) {
            int idx = tid + 256 * m;
            int r = idx >> 5, c4 = (idx & 31) << 2;
            float4 v = *(const float4*)(Hb + (size_t)(q0 + r) * HDIM + c4);
            *(float4*)(sh_hq + r * 132 + c4) = v;
        }
        if (tid < 64) sh_iq[tid] = ivb[q0 + tid];
        __syncthreads();

        // ---- stage 1: S tile (64x64), k-vectorized float4, strided 4x4 micro
        float sa[4][4];
#pragma unroll
        for (int i = 0; i < 4; i++)
#pragma unroll
            for (int j = 0; j < 4; j++) sa[i][j] = 0.0f;

        for (int k = 0; k < 128; k += 4) {
            float4 av[4], bv[4];
#pragma unroll
            for (int i = 0; i < 4; i++)
                av[i] = *(const float4*)(sh_hp + (tp + 16 * i) * 132 + k);
#pragma unroll
            for (int j = 0; j < 4; j++)
                bv[j] = *(const float4*)(sh_hq + (tq + 16 * j) * 132 + k);
#pragma unroll
            for (int i = 0; i < 4; i++)
#pragma unroll
                for (int j = 0; j < 4; j++) {
                    sa[i][j] = fmaf(av[i].x, bv[j].x, sa[i][j]);
                    sa[i][j] = fmaf(av[i].y, bv[j].y, sa[i][j]);
                    sa[i][j] = fmaf(av[i].z, bv[j].z, sa[i][j]);
                    sa[i][j] = fmaf(av[i].w, bv[j].w, sa[i][j]);
                }
        }

        // Fold inv_q and edge_weight, write S
#pragma unroll
        for (int i = 0; i < 4; i++) {
            int r = tp + 16 * i;
            const float* ewrow = EWb + (size_t)(p0 + r) * NSEQ + q0;
#pragma unroll
            for (int j = 0; j < 4; j++) {
                int qc = tq + 16 * j;
                sh_S[r * 68 + qc] = sa[i][j] * sh_iq[qc] * ewrow[qc];
            }
        }
        __syncthreads();

        // ---- stage 2: oacc += S @ hq   (8x4 micro-tile per thread)
#pragma unroll 2
        for (int q = 0; q < 64; q++) {
            float4 hv = *(const float4*)(sh_hq + q * 132 + cx * 4);
#pragma unroll
            for (int i = 0; i < 8; i++) {
                float sv = sh_S[(8 * py + i) * 68 + q];   // broadcast
                oacc[i][0] = fmaf(sv, hv.x, oacc[i][0]);
                oacc[i][1] = fmaf(sv, hv.y, oacc[i][1]);
                oacc[i][2] = fmaf(sv, hv.z, oacc[i][2]);
                oacc[i][3] = fmaf(sv, hv.w, oacc[i][3]);
            }
        }
        __syncthreads();
    }

    // Epilogue
    float* Ob = OUT + (size_t)b * NSEQ * HDIM;
#pragma unroll
    for (int i = 0; i < 8; i++) {
        int r = p0 + 8 * py + i;
        float4 o;
        if (RELU) {
            o.x = fmaxf(oacc[i][0], 0.0f); o.y = fmaxf(oacc[i][1], 0.0f);
            o.z = fmaxf(oacc[i][2], 0.0f); o.w = fmaxf(oacc[i][3], 0.0f);
        } else {
            o.x = oacc[i][0]; o.y = oacc[i][1]; o.z = oacc[i][2]; o.w = oacc[i][3];
        }
        *(float4*)(Ob + (size_t)r * HDIM + cx * 4) = o;
    }
}

// ---------------------------------------------------------------------------
extern "C" void kernel_launch(void* const* d_in, const int* in_sizes, int n_in,
                              void* d_out, int out_size)
{
    const float* x  = (const float*)d_in[0];
    const float* ew = (const float*)d_in[1];
    const float* W0 = (const float*)d_in[2];
    const float* b0 = (const float*)d_in[3];
    const float* W1 = (const float*)d_in[4];
    const float* b1 = (const float*)d_in[5];
    const float* W2 = (const float*)d_in[6];
    const float* b2 = (const float*)d_in[7];
    float* out = (float*)d_out;

    float *A, *B, *IV;
    cudaGetSymbolAddress((void**)&A,  g_A);
    cudaGetSymbolAddress((void**)&B,  g_B);
    cudaGetSymbolAddress((void**)&IV, g_inv);

    const int smem = SMEM_FLOATS * sizeof(float);   // 85248 B
    cudaFuncSetAttribute(agg_kernel<true>,
                         cudaFuncAttributeMaxDynamicSharedMemorySize, smem);
    cudaFuncSetAttribute(agg_kernel<false>,
                         cudaFuncAttributeMaxDynamicSharedMemorySize, smem);

    dim3 gGemm(NROWS / 64);           // 256
    dim3 gAgg(NSEQ / 64, BATCH);      // (32, 8)

    // Layer 0
    gemm_norm_kernel<<<gGemm, 256>>>(x, W0, b0, A, IV);
    agg_kernel<true><<<gAgg, 256, smem>>>(A, ew, IV, B);
    // Layer 1
    gemm_norm_kernel<<<gGemm, 256>>>(B, W1, b1, A, IV);
    agg_kernel<true><<<gAgg, 256, smem>>>(A, ew, IV, B);
    // Layer 2 (no ReLU)
    gemm_norm_kernel<<<gGemm, 256>>>(B, W2, b2, A, IV);
    agg_kernel<false><<<gAgg, 256, smem>>>(A, ew, IV, out);
}

// round 7
// speedup vs baseline: 1.0368x; 1.0368x over previous
#include <cuda_runtime.h>
#include <math.h>

// Problem constants
#define BATCH 8
#define NSEQ  2048
#define HDIM  128
#define NROWS (BATCH * NSEQ)   // 16384

// Scratch (device globals: no allocation allowed)
__device__ float g_A[NROWS * HDIM];
__device__ float g_B[NROWS * HDIM];
__device__ float g_inv[NROWS];

// Packed fp32x2 FMA (Blackwell sm_100+/103a): d = a*b + d, 2 fp32 lanes per instr.
__device__ __forceinline__ void fma2(unsigned long long& d,
                                     unsigned long long a,
                                     unsigned long long b) {
    asm("fma.rn.f32x2 %0, %1, %2, %0;" : "+l"(d) : "l"(a), "l"(b));
}
__device__ __forceinline__ float lo32(unsigned long long v) {
    return __uint_as_float((unsigned)v);
}
__device__ __forceinline__ float hi32(unsigned long long v) {
    return __uint_as_float((unsigned)(v >> 32));
}

// ---------------------------------------------------------------------------
// Kernel 1: H = X @ W + b, plus per-row inverse L2 norm. (tiny: ~3% of time)
// ---------------------------------------------------------------------------
__global__ __launch_bounds__(256, 2)
void gemm_norm_kernel(const float* __restrict__ X, const float* __restrict__ W,
                      const float* __restrict__ bias, float* __restrict__ H,
                      float* __restrict__ invn)
{
    __shared__ float xs[64 * 132];
    const int tid = threadIdx.x;
    const int row0 = blockIdx.x * 64;

#pragma unroll
    for (int m = 0; m < 8; m++) {
        int idx = tid + 256 * m;
        int r = idx >> 5, c4 = (idx & 31) << 2;
        float4 v = *(const float4*)(X + (size_t)(row0 + r) * HDIM + c4);
        *(float4*)(xs + r * 132 + c4) = v;
    }
    __syncthreads();

    const int cx = tid & 31;
    const int ry = tid >> 5;

    float4 b4 = *(const float4*)(bias + cx * 4);
    float acc[8][4];
#pragma unroll
    for (int i = 0; i < 8; i++) {
        acc[i][0] = b4.x; acc[i][1] = b4.y; acc[i][2] = b4.z; acc[i][3] = b4.w;
    }

#pragma unroll 4
    for (int k = 0; k < 128; k++) {
        float4 w4 = *(const float4*)(W + k * HDIM + cx * 4);
#pragma unroll
        for (int i = 0; i < 8; i++) {
            float xv = xs[(8 * ry + i) * 132 + k];
            acc[i][0] = fmaf(xv, w4.x, acc[i][0]);
            acc[i][1] = fmaf(xv, w4.y, acc[i][1]);
            acc[i][2] = fmaf(xv, w4.z, acc[i][2]);
            acc[i][3] = fmaf(xv, w4.w, acc[i][3]);
        }
    }

#pragma unroll
    for (int i = 0; i < 8; i++) {
        int r = row0 + 8 * ry + i;
        float ss = acc[i][0] * acc[i][0] + acc[i][1] * acc[i][1]
                 + acc[i][2] * acc[i][2] + acc[i][3] * acc[i][3];
#pragma unroll
        for (int o = 16; o > 0; o >>= 1) ss += __shfl_xor_sync(0xffffffffu, ss, o);
        if (cx == 0) invn[r] = 1.0f / fmaxf(sqrtf(ss), 1e-12f);
        float4 o4 = make_float4(acc[i][0], acc[i][1], acc[i][2], acc[i][3]);
        *(float4*)(H + (size_t)r * HDIM + cx * 4) = o4;
    }
}

// ---------------------------------------------------------------------------
// Kernel 2: fused  out[p,:] = sum_q ew[p,q] * (nh_p . nh_q) * h[q,:]
// All inner-loop math via packed fma.rn.f32x2 (2x fp32 MAC rate).
//   stage 1: k-packed dot products -> S (stored DUPLICATED as (s,s) pairs)
//   stage 2: column-packed  oacc += S @ hq
// ---------------------------------------------------------------------------
// smem: hp[64][132] + hq[64][132] + S2[64][136] + iq[64]
#define SMEM_FLOATS (8448 + 8448 + 8704 + 64)    // 25664 floats = 102656 B

template<bool RELU>
__global__ __launch_bounds__(256, 2)
void agg_kernel(const float* __restrict__ H, const float* __restrict__ EW,
                const float* __restrict__ invn, float* __restrict__ OUT)
{
    extern __shared__ float sm[];
    float* sh_hp = sm;               // [64][132], pre-scaled by inv_p
    float* sh_hq = sm + 8448;        // [64][132], raw
    float* sh_S2 = sm + 16896;       // [64][136]: S duplicated (s,s) pairs
    float* sh_iq = sm + 25600;       // [64]

    const int tid = threadIdx.x;
    const int b   = blockIdx.y;
    const int p0  = blockIdx.x * 64;
    const float* Hb  = H + (size_t)b * NSEQ * HDIM;
    const float* ivb = invn + b * NSEQ;
    const float* EWb = EW + (size_t)b * NSEQ * NSEQ;

    // Load hp tile, folding inv_p
#pragma unroll
    for (int m = 0; m < 8; m++) {
        int idx = tid + 256 * m;
        int r = idx >> 5, c4 = (idx & 31) << 2;
        float iv = ivb[p0 + r];
        float4 v = *(const float4*)(Hb + (size_t)(p0 + r) * HDIM + c4);
        v.x *= iv; v.y *= iv; v.z *= iv; v.w *= iv;
        *(float4*)(sh_hp + r * 132 + c4) = v;
    }

    const int tq = tid & 15, tp = tid >> 4;   // stage-1: 16x16 grid, 4x4 micro
    const int cx = tid & 31, py = tid >> 5;   // stage-2: warp = fixed py

    // Column-packed output accumulators: 8 rows x 2 packed pairs (4 cols)
    unsigned long long oacc2[8][2];
#pragma unroll
    for (int i = 0; i < 8; i++) { oacc2[i][0] = 0ULL; oacc2[i][1] = 0ULL; }

    __syncthreads();

    for (int qt = 0; qt < 32; qt++) {
        const int q0 = qt * 64;

        // Load hq tile (raw) + inv_q
#pragma unroll
        for (int m = 0; m < 8; m++) {
            int idx = tid + 256 * m;
            int r = idx >> 5, c4 = (idx & 31) << 2;
            float4 v = *(const float4*)(Hb + (size_t)(q0 + r) * HDIM + c4);
            *(float4*)(sh_hq + r * 132 + c4) = v;
        }
        if (tid < 64) sh_iq[tid] = ivb[q0 + tid];
        __syncthreads();

        // ---- stage 1: S tile (64x64), k-packed f32x2 dot products
        unsigned long long sa2[4][4];
#pragma unroll
        for (int i = 0; i < 4; i++)
#pragma unroll
            for (int j = 0; j < 4; j++) sa2[i][j] = 0ULL;

        for (int k = 0; k < 128; k += 4) {
            ulonglong2 a2[4], b2[4];
#pragma unroll
            for (int i = 0; i < 4; i++)
                a2[i] = *(const ulonglong2*)(sh_hp + (tp + 16 * i) * 132 + k);
#pragma unroll
            for (int j = 0; j < 4; j++)
                b2[j] = *(const ulonglong2*)(sh_hq + (tq + 16 * j) * 132 + k);
#pragma unroll
            for (int i = 0; i < 4; i++)
#pragma unroll
                for (int j = 0; j < 4; j++) {
                    fma2(sa2[i][j], a2[i].x, b2[j].x);
                    fma2(sa2[i][j], a2[i].y, b2[j].y);
                }
        }

        // Fold inv_q and edge_weight; write S duplicated as (s,s)
#pragma unroll
        for (int i = 0; i < 4; i++) {
            int r = tp + 16 * i;
            const float* ewrow = EWb + (size_t)(p0 + r) * NSEQ + q0;
#pragma unroll
            for (int j = 0; j < 4; j++) {
                int qc = tq + 16 * j;
                float s = (lo32(sa2[i][j]) + hi32(sa2[i][j]))
                        * sh_iq[qc] * ewrow[qc];
                *(float2*)(sh_S2 + r * 136 + 2 * qc) = make_float2(s, s);
            }
        }
        __syncthreads();

        // ---- stage 2: oacc += S @ hq  (packed over output columns)
#pragma unroll 2
        for (int q = 0; q < 64; q++) {
            ulonglong2 h2 = *(const ulonglong2*)(sh_hq + q * 132 + cx * 4);
#pragma unroll
            for (int i = 0; i < 8; i++) {
                unsigned long long sv2 =
                    *(const unsigned long long*)(sh_S2 + (8 * py + i) * 136 + 2 * q);
                fma2(oacc2[i][0], sv2, h2.x);
                fma2(oacc2[i][1], sv2, h2.y);
            }
        }
        __syncthreads();
    }

    // Epilogue
    float* Ob = OUT + (size_t)b * NSEQ * HDIM;
#pragma unroll
    for (int i = 0; i < 8; i++) {
        int r = p0 + 8 * py + i;
        float4 o;
        o.x = lo32(oacc2[i][0]); o.y = hi32(oacc2[i][0]);
        o.z = lo32(oacc2[i][1]); o.w = hi32(oacc2[i][1]);
        if (RELU) {
            o.x = fmaxf(o.x, 0.0f); o.y = fmaxf(o.y, 0.0f);
            o.z = fmaxf(o.z, 0.0f); o.w = fmaxf(o.w, 0.0f);
        }
        *(float4*)(Ob + (size_t)r * HDIM + cx * 4) = o;
    }
}

// ---------------------------------------------------------------------------
extern "C" void kernel_launch(void* const* d_in, const int* in_sizes, int n_in,
                              void* d_out, int out_size)
{
    const float* x  = (const float*)d_in[0];
    const float* ew = (const float*)d_in[1];
    const float* W0 = (const float*)d_in[2];
    const float* b0 = (const float*)d_in[3];
    const float* W1 = (const float*)d_in[4];
    const float* b1 = (const float*)d_in[5];
    const float* W2 = (const float*)d_in[6];
    const float* b2 = (const float*)d_in[7];
    float* out = (float*)d_out;

    float *A, *B, *IV;
    cudaGetSymbolAddress((void**)&A,  g_A);
    cudaGetSymbolAddress((void**)&B,  g_B);
    cudaGetSymbolAddress((void**)&IV, g_inv);

    const int smem = SMEM_FLOATS * sizeof(float);   // 102656 B
    cudaFuncSetAttribute(agg_kernel<true>,
                         cudaFuncAttributeMaxDynamicSharedMemorySize, smem);
    cudaFuncSetAttribute(agg_kernel<false>,
                         cudaFuncAttributeMaxDynamicSharedMemorySize, smem);

    dim3 gGemm(NROWS / 64);           // 256
    dim3 gAgg(NSEQ / 64, BATCH);      // (32, 8)

    // Layer 0
    gemm_norm_kernel<<<gGemm, 256>>>(x, W0, b0, A, IV);
    agg_kernel<true><<<gAgg, 256, smem>>>(A, ew, IV, B);
    // Layer 1
    gemm_norm_kernel<<<gGemm, 256>>>(B, W1, b1, A, IV);
    agg_kernel<true><<<gAgg, 256, smem>>>(A, ew, IV, B);
    // Layer 2 (no ReLU)
    gemm_norm_kernel<<<gGemm, 256>>>(B, W2, b2, A, IV);
    agg_kernel<false><<<gAgg, 256, smem>>>(A, ew, IV, out);
}